// round 14
// baseline (speedup 1.0000x reference)
#include <cuda_runtime.h>
#include <cuda_bf16.h>
#include <math.h>

#define NN 4096
#define EE 16384
#define PHID 64
#define EPSF 1e-8f
#define CAP 32

// Q = round(B/scale_r) int8 (16MB, L2-resident); per-row c = scale_r/d_r.
__device__ char g_Q[(size_t)NN * NN];
__device__ float g_c[NN];
// grouping state: all starts zero (BSS) and is restored every call.
__device__ int g_cnt[2 * NN];          // per-(layer,node) degree, consumed by k_mid
__device__ int g_list[2 * NN * CAP];   // per-(layer,node) edge ids
__device__ int2 g_slot[2 * EE];        // grouped slots: (eid, widx)
__device__ int g_total;                // cursor/total; zeroed by k_prep

// ---------------------------------------------------------------------------
// k_prep: R11 measured-best body + free-ish edge-list append (R6).
// ---------------------------------------------------------------------------
__global__ __launch_bounds__(256) void k_prep(const float* __restrict__ A,
                                              const float* __restrict__ f0,
                                              const float* __restrict__ f1,
                                              const int* __restrict__ src0,
                                              const int* __restrict__ src1) {
    __shared__ float rsum[2][8];
    __shared__ float rmax[2][8];
    __shared__ float s_cinv[2];
    int tid = threadIdx.x;
    int wid = tid >> 5, lane = tid & 31;

    if (blockIdx.x == 0 && tid == 16) g_total = 0;

    // append: 2048 CTAs x 16 edges = 32768 = 2*EE
    if (tid < 16) {
        int idx = blockIdx.x * 16 + tid;
        int layer = idx >> 14;
        int e = idx & (EE - 1);
        int s = layer ? __ldg(src1 + e) : __ldg(src0 + e);
        int slot = layer * NN + s;
        int pos = atomicAdd(&g_cnt[slot], 1);
        if (pos < CAP) g_list[slot * CAP + pos] = e;
    }

    float4 f[4];
#pragma unroll
    for (int it = 0; it < 4; ++it) {
        int q = tid + it * 256;
        float4 a = ((const float4*)f0)[q];
        float4 b = ((const float4*)f1)[q];
        f[it].x = 0.5f * (a.x + b.x);
        f[it].y = 0.5f * (a.y + b.y);
        f[it].z = 0.5f * (a.z + b.z);
        f[it].w = 0.5f * (a.w + b.w);
    }

    float4 m[2][4];
    float acc[2], vmax[2];
#pragma unroll
    for (int r = 0; r < 2; ++r) {
        int row = blockIdx.x * 2 + r;
        const float4* a4 = (const float4*)(A + (size_t)row * NN);
        acc[r] = 0.f;
        vmax[r] = 0.f;
#pragma unroll
        for (int it = 0; it < 4; ++it) {
            float4 v = a4[tid + it * 256];
            m[r][it].x = v.x * f[it].x;
            m[r][it].y = v.y * f[it].y;
            m[r][it].z = v.z * f[it].z;
            m[r][it].w = v.w * f[it].w;
            float e0 = m[r][it].x + EPSF, e1 = m[r][it].y + EPSF;
            float e2 = m[r][it].z + EPSF, e3 = m[r][it].w + EPSF;
            acc[r] += e0 * e0 + e1 * e1 + e2 * e2 + e3 * e3;
            vmax[r] = fmaxf(vmax[r],
                            fmaxf(fmaxf(fabsf(m[r][it].x), fabsf(m[r][it].y)),
                                  fmaxf(fabsf(m[r][it].z), fabsf(m[r][it].w))));
        }
    }
#pragma unroll
    for (int off = 16; off; off >>= 1) {
#pragma unroll
        for (int r = 0; r < 2; ++r) {
            acc[r] += __shfl_xor_sync(0xffffffffu, acc[r], off);
            vmax[r] = fmaxf(vmax[r], __shfl_xor_sync(0xffffffffu, vmax[r], off));
        }
    }
    if (lane == 0) {
#pragma unroll
        for (int r = 0; r < 2; ++r) {
            rsum[r][wid] = acc[r];
            rmax[r][wid] = vmax[r];
        }
    }
    __syncthreads();
    if (tid < 2) {
        float t = 0.f, mx = 0.f;
#pragma unroll
        for (int w = 0; w < 8; w++) {
            t += rsum[tid][w];
            mx = fmaxf(mx, rmax[tid][w]);
        }
        float scale = fmaxf(mx, 1e-20f) * (1.0f / 127.0f);
        g_c[blockIdx.x * 2 + tid] = scale / sqrtf(t);
        s_cinv[tid] = 1.0f / scale;
    }
    __syncthreads();

#pragma unroll
    for (int r = 0; r < 2; ++r) {
        float inv_scale = s_cinv[r];
        uchar4 pk[4];
#pragma unroll
        for (int it = 0; it < 4; ++it) {
            int q0 = __float2int_rn(m[r][it].x * inv_scale);
            int q1 = __float2int_rn(m[r][it].y * inv_scale);
            int q2 = __float2int_rn(m[r][it].z * inv_scale);
            int q3 = __float2int_rn(m[r][it].w * inv_scale);
            pk[it].x = (unsigned char)(char)max(-127, min(127, q0));
            pk[it].y = (unsigned char)(char)max(-127, min(127, q1));
            pk[it].z = (unsigned char)(char)max(-127, min(127, q2));
            pk[it].w = (unsigned char)(char)max(-127, min(127, q3));
        }
        uint4 o;
        o.x = *(unsigned*)&pk[0];
        o.y = *(unsigned*)&pk[1];
        o.z = *(unsigned*)&pk[2];
        o.w = *(unsigned*)&pk[3];
        ((uint4*)(g_Q + (size_t)(blockIdx.x * 2 + r) * NN))[tid] = o;
    }
}

// ---------------------------------------------------------------------------
// k_mid: one thread per (layer,node). Grouping WITHOUT ordering: grab a
// contiguous block of slots via one atomic bump, emit (eid, widx) pairs.
// Consumes + rezeroes counters (replay invariant).
// ---------------------------------------------------------------------------
__global__ __launch_bounds__(256) void k_mid() {
    int i = blockIdx.x * 256 + threadIdx.x;  // 0..8191
    int deg = min(g_cnt[i], CAP);
    g_cnt[i] = 0;
    int base = atomicAdd(&g_total, deg);
#pragma unroll 1
    for (int k = 0; k < deg; ++k)
        g_slot[base + k] = make_int2(g_list[i * CAP + k], i);
}

// ---------------------------------------------------------------------------
// k_edge: dual-edge warps over GROUPED slots. One int4 load gives both
// (eid,widx) pairs; consecutive slots usually share the src node -> src row
// LDGs merge in L1 (traffic 268 -> ~180MB). Body = R12 (measured best).
// ---------------------------------------------------------------------------
__global__ __launch_bounds__(256) void k_edge(
    const int* __restrict__ dst0, const int* __restrict__ dst1,
    const float* __restrict__ p1w1, const float* __restrict__ p1b1,
    const float* __restrict__ p1w2, const float* __restrict__ p1b2,
    const float* __restrict__ p2w1, const float* __restrict__ p2b1,
    const float* __restrict__ p2w2, const float* __restrict__ p2b2,
    float* __restrict__ out) {
    int w = (int)((blockIdx.x * blockDim.x + threadIdx.x) >> 5);  // 0..16383
    int lane = threadIdx.x & 31;
    int total = __ldg(&g_total);
    if (2 * w >= total) return;          // warp-uniform
    bool h1 = (2 * w + 1) < total;       // warp-uniform

    int4 q = __ldg((const int4*)g_slot + w);  // (eidA,widxA,eidB,widxB)
    int eidA = q.x, widxA = q.y;
    int eidB = h1 ? q.z : q.x;
    int widxB = h1 ? q.w : q.y;

    int layerA = widxA >> 12, sA = widxA & (NN - 1);
    int layerB = widxB >> 12, sB = widxB & (NN - 1);
    int tA = layerA ? __ldg(dst1 + eidA) : __ldg(dst0 + eidA);
    int tB = layerB ? __ldg(dst1 + eidB) : __ldg(dst0 + eidB);

    const uint4* psA = (const uint4*)(g_Q + (size_t)sA * NN) + lane;
    const uint4* ptA = (const uint4*)(g_Q + (size_t)tA * NN) + lane;
    const uint4* psB = (const uint4*)(g_Q + (size_t)sB * NN) + lane;
    const uint4* ptB = (const uint4*)(g_Q + (size_t)tB * NN) + lane;

    int a0 = 0, a1 = 0, a2 = 0, a3 = 0;
    int b0 = 0, b1 = 0, b2 = 0, b3 = 0;
#pragma unroll
    for (int k = 0; k < 8; k++) {
        uint4 xa = psA[k * 32];
        uint4 xb = ptA[k * 32];
        uint4 ya = psB[k * 32];
        uint4 yb = ptB[k * 32];
        a0 = __dp4a((int)xa.x, (int)xb.x, a0);
        b0 = __dp4a((int)ya.x, (int)yb.x, b0);
        a1 = __dp4a((int)xa.y, (int)xb.y, a1);
        b1 = __dp4a((int)ya.y, (int)yb.y, b1);
        a2 = __dp4a((int)xa.z, (int)xb.z, a2);
        b2 = __dp4a((int)ya.z, (int)yb.z, b2);
        a3 = __dp4a((int)xa.w, (int)xb.w, a3);
        b3 = __dp4a((int)ya.w, (int)yb.w, b3);
    }
    int accA = (a0 + a1) + (a2 + a3);
    int accB = (b0 + b1) + (b2 + b3);
    accA = __reduce_add_sync(0xffffffffu, accA);
    accB = __reduce_add_sync(0xffffffffu, accB);

    float x0 = (float)accA * g_c[sA] * g_c[tA];
    float x1 = (float)accB * g_c[sB] * g_c[tB];

    int oA = layerA * PHID, oB = layerB * PHID;

    // MLP 1 for both edges, interleaved (per-edge weights: layers may differ)
    float h0A = fmaxf(fmaf(x0, p1w1[oA + lane], p1b1[oA + lane]), 0.f);
    float h0B = fmaxf(fmaf(x1, p1w1[oB + lane], p1b1[oB + lane]), 0.f);
    float h1A = fmaxf(fmaf(x0, p1w1[oA + lane + 32], p1b1[oA + lane + 32]), 0.f);
    float h1B = fmaxf(fmaf(x1, p1w1[oB + lane + 32], p1b1[oB + lane + 32]), 0.f);
    float yA = fmaf(h0A, p1w2[oA + lane], h1A * p1w2[oA + lane + 32]);
    float yB = fmaf(h0B, p1w2[oB + lane], h1B * p1w2[oB + lane + 32]);
#pragma unroll
    for (int off = 16; off; off >>= 1) {
        yA += __shfl_xor_sync(0xffffffffu, yA, off);
        yB += __shfl_xor_sync(0xffffffffu, yB, off);
    }
    float x2A = 0.5f * (yA + p1b2[layerA]);
    float x2B = 0.5f * (yB + p1b2[layerB]);

    // MLP 2 for both edges, interleaved
    float g0A = fmaxf(fmaf(x2A, p2w1[oA + lane], p2b1[oA + lane]), 0.f);
    float g0B = fmaxf(fmaf(x2B, p2w1[oB + lane], p2b1[oB + lane]), 0.f);
    float g1A = fmaxf(fmaf(x2A, p2w1[oA + lane + 32], p2b1[oA + lane + 32]), 0.f);
    float g1B = fmaxf(fmaf(x2B, p2w1[oB + lane + 32], p2b1[oB + lane + 32]), 0.f);
    float zA = fmaf(g0A, p2w2[oA + lane], g1A * p2w2[oA + lane + 32]);
    float zB = fmaf(g0B, p2w2[oB + lane], g1B * p2w2[oB + lane + 32]);
#pragma unroll
    for (int off = 16; off; off >>= 1) {
        zA += __shfl_xor_sync(0xffffffffu, zA, off);
        zB += __shfl_xor_sync(0xffffffffu, zB, off);
    }
    zA += p2b2[layerA];
    zB += p2b2[layerB];

    if (lane == 0) {
        out[layerA * EE + eidA] = zA;
        if (h1) out[layerB * EE + eidB] = zB;
    }
}

extern "C" void kernel_launch(void* const* d_in, const int* in_sizes, int n_in,
                              void* d_out, int out_size) {
    const float* A    = (const float*)d_in[0];
    const int* src0   = (const int*)d_in[1];
    const int* dst0   = (const int*)d_in[2];
    const int* src1   = (const int*)d_in[3];
    const int* dst1   = (const int*)d_in[4];
    const float* f0   = (const float*)d_in[5];
    const float* f1   = (const float*)d_in[6];
    const float* p1w1 = (const float*)d_in[7];
    const float* p1b1 = (const float*)d_in[8];
    const float* p1w2 = (const float*)d_in[9];
    const float* p1b2 = (const float*)d_in[10];
    const float* p2w1 = (const float*)d_in[11];
    const float* p2b1 = (const float*)d_in[12];
    const float* p2w2 = (const float*)d_in[13];
    const float* p2b2 = (const float*)d_in[14];
    float* out = (float*)d_out;

    k_prep<<<NN / 2, 256>>>(A, f0, f1, src0, src1);
    k_mid<<<32, 256>>>();
    // 16384 dual-edge warps, 8 per 256-thread CTA
    k_edge<<<2048, 256>>>(dst0, dst1,
                          p1w1, p1b1, p1w2, p1b2,
                          p2w1, p2b1, p2w2, p2b2, out);
}

// round 15
// speedup vs baseline: 1.0662x; 1.0662x over previous
#include <cuda_runtime.h>
#include <cuda_bf16.h>
#include <math.h>

#define NN 4096
#define EE 16384
#define PHID 64
#define EPSF 1e-8f
#define CAP 32

// Q = round(B/scale_r) int8 (16MB, L2-resident); per-row c = scale_r/d_r.
__device__ char g_Q[(size_t)NN * NN];
__device__ float g_c[NN];
// grouping state: all starts zero (BSS) and is restored every call.
__device__ int g_cnt[2 * NN];          // per-(layer,node) degree, consumed by k_mid
__device__ int g_list[2 * NN * CAP];   // per-(layer,node) edge ids
__device__ int g_slot[2 * EE];         // grouped packed slots: eid | widx<<14
__device__ int g_total;                // cursor/total; zeroed by k_prep

// ---------------------------------------------------------------------------
// k_prep: R11 body + edge-list append; __launch_bounds__(256,5) pins 5 CTAs/SM
// (51-reg target, ~3 L1-backed spills hidden under DRAM latency).
// ---------------------------------------------------------------------------
__global__ __launch_bounds__(256, 5) void k_prep(const float* __restrict__ A,
                                                 const float* __restrict__ f0,
                                                 const float* __restrict__ f1,
                                                 const int* __restrict__ src0,
                                                 const int* __restrict__ src1) {
    __shared__ float rsum[2][8];
    __shared__ float rmax[2][8];
    __shared__ float s_cinv[2];
    int tid = threadIdx.x;
    int wid = tid >> 5, lane = tid & 31;

    if (blockIdx.x == 0 && tid == 16) g_total = 0;

    // append: 2048 CTAs x 16 edges = 32768 = 2*EE
    if (tid < 16) {
        int idx = blockIdx.x * 16 + tid;
        int layer = idx >> 14;
        int e = idx & (EE - 1);
        int s = layer ? __ldg(src1 + e) : __ldg(src0 + e);
        int slot = layer * NN + s;
        int pos = atomicAdd(&g_cnt[slot], 1);
        if (pos < CAP) g_list[slot * CAP + pos] = e;
    }

    float4 f[4];
#pragma unroll
    for (int it = 0; it < 4; ++it) {
        int q = tid + it * 256;
        float4 a = ((const float4*)f0)[q];
        float4 b = ((const float4*)f1)[q];
        f[it].x = 0.5f * (a.x + b.x);
        f[it].y = 0.5f * (a.y + b.y);
        f[it].z = 0.5f * (a.z + b.z);
        f[it].w = 0.5f * (a.w + b.w);
    }

    float4 m[2][4];
    float acc[2], vmax[2];
#pragma unroll
    for (int r = 0; r < 2; ++r) {
        int row = blockIdx.x * 2 + r;
        const float4* a4 = (const float4*)(A + (size_t)row * NN);
        acc[r] = 0.f;
        vmax[r] = 0.f;
#pragma unroll
        for (int it = 0; it < 4; ++it) {
            float4 v = a4[tid + it * 256];
            m[r][it].x = v.x * f[it].x;
            m[r][it].y = v.y * f[it].y;
            m[r][it].z = v.z * f[it].z;
            m[r][it].w = v.w * f[it].w;
            float e0 = m[r][it].x + EPSF, e1 = m[r][it].y + EPSF;
            float e2 = m[r][it].z + EPSF, e3 = m[r][it].w + EPSF;
            acc[r] += e0 * e0 + e1 * e1 + e2 * e2 + e3 * e3;
            vmax[r] = fmaxf(vmax[r],
                            fmaxf(fmaxf(fabsf(m[r][it].x), fabsf(m[r][it].y)),
                                  fmaxf(fabsf(m[r][it].z), fabsf(m[r][it].w))));
        }
    }
#pragma unroll
    for (int off = 16; off; off >>= 1) {
#pragma unroll
        for (int r = 0; r < 2; ++r) {
            acc[r] += __shfl_xor_sync(0xffffffffu, acc[r], off);
            vmax[r] = fmaxf(vmax[r], __shfl_xor_sync(0xffffffffu, vmax[r], off));
        }
    }
    if (lane == 0) {
#pragma unroll
        for (int r = 0; r < 2; ++r) {
            rsum[r][wid] = acc[r];
            rmax[r][wid] = vmax[r];
        }
    }
    __syncthreads();
    if (tid < 2) {
        float t = 0.f, mx = 0.f;
#pragma unroll
        for (int w = 0; w < 8; w++) {
            t += rsum[tid][w];
            mx = fmaxf(mx, rmax[tid][w]);
        }
        float scale = fmaxf(mx, 1e-20f) * (1.0f / 127.0f);
        g_c[blockIdx.x * 2 + tid] = scale / sqrtf(t);
        s_cinv[tid] = 1.0f / scale;
    }
    __syncthreads();

#pragma unroll
    for (int r = 0; r < 2; ++r) {
        float inv_scale = s_cinv[r];
        uchar4 pk[4];
#pragma unroll
        for (int it = 0; it < 4; ++it) {
            int q0 = __float2int_rn(m[r][it].x * inv_scale);
            int q1 = __float2int_rn(m[r][it].y * inv_scale);
            int q2 = __float2int_rn(m[r][it].z * inv_scale);
            int q3 = __float2int_rn(m[r][it].w * inv_scale);
            pk[it].x = (unsigned char)(char)max(-127, min(127, q0));
            pk[it].y = (unsigned char)(char)max(-127, min(127, q1));
            pk[it].z = (unsigned char)(char)max(-127, min(127, q2));
            pk[it].w = (unsigned char)(char)max(-127, min(127, q3));
        }
        uint4 o;
        o.x = *(unsigned*)&pk[0];
        o.y = *(unsigned*)&pk[1];
        o.z = *(unsigned*)&pk[2];
        o.w = *(unsigned*)&pk[3];
        ((uint4*)(g_Q + (size_t)(blockIdx.x * 2 + r) * NN))[tid] = o;
    }
}

// ---------------------------------------------------------------------------
// k_mid: one thread per (layer,node); grab contiguous slot block via one
// atomic bump; emit packed (eid | widx<<14). Consumes + rezeroes counters.
// ---------------------------------------------------------------------------
__global__ __launch_bounds__(256) void k_mid() {
    int i = blockIdx.x * 256 + threadIdx.x;  // 0..8191
    int deg = min(g_cnt[i], CAP);
    g_cnt[i] = 0;
    int base = atomicAdd(&g_total, deg);
    int hi = i << 14;
#pragma unroll 1
    for (int k = 0; k < deg; ++k)
        g_slot[base + k] = g_list[i * CAP + k] | hi;
}

// ---------------------------------------------------------------------------
// k_edge: dual-edge warps over GROUPED packed slots (one int2 load = both).
// Consecutive slots usually share the src node -> src LDGs merge in L1
// (traffic 268 -> ~180MB; measured edge ~14.5us in R14).
// ---------------------------------------------------------------------------
__global__ __launch_bounds__(256) void k_edge(
    const int* __restrict__ dst0, const int* __restrict__ dst1,
    const float* __restrict__ p1w1, const float* __restrict__ p1b1,
    const float* __restrict__ p1w2, const float* __restrict__ p1b2,
    const float* __restrict__ p2w1, const float* __restrict__ p2b1,
    const float* __restrict__ p2w2, const float* __restrict__ p2b2,
    float* __restrict__ out) {
    int w = (int)((blockIdx.x * blockDim.x + threadIdx.x) >> 5);  // 0..16383
    int lane = threadIdx.x & 31;
    int total = __ldg(&g_total);
    if (2 * w >= total) return;          // warp-uniform
    bool h1 = (2 * w + 1) < total;       // warp-uniform

    int2 q = __ldg((const int2*)g_slot + w);
    int pB = h1 ? q.y : q.x;
    int eidA = q.x & (EE - 1), widxA = q.x >> 14;
    int eidB = pB & (EE - 1), widxB = pB >> 14;

    int layerA = widxA >> 12, sA = widxA & (NN - 1);
    int layerB = widxB >> 12, sB = widxB & (NN - 1);
    int tA = layerA ? __ldg(dst1 + eidA) : __ldg(dst0 + eidA);
    int tB = layerB ? __ldg(dst1 + eidB) : __ldg(dst0 + eidB);

    const uint4* psA = (const uint4*)(g_Q + (size_t)sA * NN) + lane;
    const uint4* ptA = (const uint4*)(g_Q + (size_t)tA * NN) + lane;
    const uint4* psB = (const uint4*)(g_Q + (size_t)sB * NN) + lane;
    const uint4* ptB = (const uint4*)(g_Q + (size_t)tB * NN) + lane;

    int a0 = 0, a1 = 0, a2 = 0, a3 = 0;
    int b0 = 0, b1 = 0, b2 = 0, b3 = 0;
#pragma unroll
    for (int k = 0; k < 8; k++) {
        uint4 xa = psA[k * 32];
        uint4 xb = ptA[k * 32];
        uint4 ya = psB[k * 32];
        uint4 yb = ptB[k * 32];
        a0 = __dp4a((int)xa.x, (int)xb.x, a0);
        b0 = __dp4a((int)ya.x, (int)yb.x, b0);
        a1 = __dp4a((int)xa.y, (int)xb.y, a1);
        b1 = __dp4a((int)ya.y, (int)yb.y, b1);
        a2 = __dp4a((int)xa.z, (int)xb.z, a2);
        b2 = __dp4a((int)ya.z, (int)yb.z, b2);
        a3 = __dp4a((int)xa.w, (int)xb.w, a3);
        b3 = __dp4a((int)ya.w, (int)yb.w, b3);
    }
    int accA = (a0 + a1) + (a2 + a3);
    int accB = (b0 + b1) + (b2 + b3);
    accA = __reduce_add_sync(0xffffffffu, accA);
    accB = __reduce_add_sync(0xffffffffu, accB);

    float x0 = (float)accA * g_c[sA] * g_c[tA];
    float x1 = (float)accB * g_c[sB] * g_c[tB];

    int oA = layerA * PHID, oB = layerB * PHID;

    float h0A = fmaxf(fmaf(x0, p1w1[oA + lane], p1b1[oA + lane]), 0.f);
    float h0B = fmaxf(fmaf(x1, p1w1[oB + lane], p1b1[oB + lane]), 0.f);
    float h1A = fmaxf(fmaf(x0, p1w1[oA + lane + 32], p1b1[oA + lane + 32]), 0.f);
    float h1B = fmaxf(fmaf(x1, p1w1[oB + lane + 32], p1b1[oB + lane + 32]), 0.f);
    float yA = fmaf(h0A, p1w2[oA + lane], h1A * p1w2[oA + lane + 32]);
    float yB = fmaf(h0B, p1w2[oB + lane], h1B * p1w2[oB + lane + 32]);
#pragma unroll
    for (int off = 16; off; off >>= 1) {
        yA += __shfl_xor_sync(0xffffffffu, yA, off);
        yB += __shfl_xor_sync(0xffffffffu, yB, off);
    }
    float x2A = 0.5f * (yA + p1b2[layerA]);
    float x2B = 0.5f * (yB + p1b2[layerB]);

    float g0A = fmaxf(fmaf(x2A, p2w1[oA + lane], p2b1[oA + lane]), 0.f);
    float g0B = fmaxf(fmaf(x2B, p2w1[oB + lane], p2b1[oB + lane]), 0.f);
    float g1A = fmaxf(fmaf(x2A, p2w1[oA + lane + 32], p2b1[oA + lane + 32]), 0.f);
    float g1B = fmaxf(fmaf(x2B, p2w1[oB + lane + 32], p2b1[oB + lane + 32]), 0.f);
    float zA = fmaf(g0A, p2w2[oA + lane], g1A * p2w2[oA + lane + 32]);
    float zB = fmaf(g0B, p2w2[oB + lane], g1B * p2w2[oB + lane + 32]);
#pragma unroll
    for (int off = 16; off; off >>= 1) {
        zA += __shfl_xor_sync(0xffffffffu, zA, off);
        zB += __shfl_xor_sync(0xffffffffu, zB, off);
    }
    zA += p2b2[layerA];
    zB += p2b2[layerB];

    if (lane == 0) {
        out[layerA * EE + eidA] = zA;
        if (h1) out[layerB * EE + eidB] = zB;
    }
}

extern "C" void kernel_launch(void* const* d_in, const int* in_sizes, int n_in,
                              void* d_out, int out_size) {
    const float* A    = (const float*)d_in[0];
    const int* src0   = (const int*)d_in[1];
    const int* dst0   = (const int*)d_in[2];
    const int* src1   = (const int*)d_in[3];
    const int* dst1   = (const int*)d_in[4];
    const float* f0   = (const float*)d_in[5];
    const float* f1   = (const float*)d_in[6];
    const float* p1w1 = (const float*)d_in[7];
    const float* p1b1 = (const float*)d_in[8];
    const float* p1w2 = (const float*)d_in[9];
    const float* p1b2 = (const float*)d_in[10];
    const float* p2w1 = (const float*)d_in[11];
    const float* p2b1 = (const float*)d_in[12];
    const float* p2w2 = (const float*)d_in[13];
    const float* p2b2 = (const float*)d_in[14];
    float* out = (float*)d_out;

    k_prep<<<NN / 2, 256>>>(A, f0, f1, src0, src1);
    k_mid<<<32, 256>>>();
    k_edge<<<2048, 256>>>(dst0, dst1,
                          p1w1, p1b1, p1w2, p1b2,
                          p2w1, p2b1, p2w2, p2b2, out);
}